// round 4
// baseline (speedup 1.0000x reference)
#include <cuda_runtime.h>
#include <mma.h>
#include <cmath>

using namespace nvcuda;

#define BATCH 16
#define SEQL  512
#define DIMC  2048
#define NHEAD 16
#define HDIM  128
#define NQKV  6144
#define MTOT  (BATCH*SEQL)   // 8192

// Scratch (device globals: allocation-guard safe)
__device__ float g_q[(size_t)BATCH*NHEAD*SEQL*HDIM];  // [B,H,T,hd]
__device__ float g_k[(size_t)BATCH*NHEAD*SEQL*HDIM];
__device__ float g_v[(size_t)BATCH*NHEAD*SEQL*HDIM];
__device__ float g_y[(size_t)MTOT*DIMC];              // attention out, [B*T, C]

// ---------------------------------------------------------------------------
// TF32 GEMM, double-buffered: C[M,N] = A[M,2048] * B[2048,N]
// MODE 0: A = x, N=6144, epilogue scatters q/k/v into [B,H,T,hd] layout
// MODE 1: A = g_y, N=2048, epilogue writes Cout row-major
// ---------------------------------------------------------------------------
#define BM 128
#define BN 128
#define BK 32
#define APAD 4
#define BPAD 4
#define ALD (BK + APAD)   // 36
#define BLD (BN + BPAD)   // 132
#define GEMM_SMEM ((2*BM*ALD + 2*BK*BLD) * 4)

template<int MODE>
__global__ void __launch_bounds__(256, 2)
gemm_tf32_kernel(const float* __restrict__ A, const float* __restrict__ Bmat,
                 float* __restrict__ Cout, int N)
{
    extern __shared__ float sm[];
    float* As = sm;                       // [2][BM][ALD]
    float* Bs = sm + 2 * BM * ALD;        // [2][BK][BLD]

    const int tid  = threadIdx.x;
    const int warp = tid >> 5;
    const int wm   = warp >> 1;      // 0..3  (rows of 32)
    const int wn   = warp & 1;       // 0..1  (cols of 64)
    const int tileM = blockIdx.y * BM;
    const int tileN = blockIdx.x * BN;

    const float* Aptr = (MODE == 1) ? g_y : A;

    const int arow = tid >> 3;       // 0..31 base row (stride 32 over 4 its)
    const int ac   = (tid & 7) * 4;  // col
    const int brow = tid >> 5;       // 0..7 base row (stride 8 over 4 its)
    const int bc   = (tid & 31) * 4;

    wmma::fragment<wmma::accumulator, 16, 16, 8, float> acc[2][4];
#pragma unroll
    for (int i = 0; i < 2; i++)
#pragma unroll
        for (int j = 0; j < 4; j++) wmma::fill_fragment(acc[i][j], 0.0f);

    float4 ra[4], rb[4];

#define LOAD_TILES(k0)                                                          \
    {                                                                           \
        _Pragma("unroll")                                                       \
        for (int it = 0; it < 4; it++)                                          \
            ra[it] = *(const float4*)(Aptr + (size_t)(tileM + arow + it*32) * DIMC + (k0) + ac); \
        _Pragma("unroll")                                                       \
        for (int it = 0; it < 4; it++)                                          \
            rb[it] = *(const float4*)(Bmat + (size_t)((k0) + brow + it*8) * N + tileN + bc); \
    }

#define STORE_TILES(st)                                                         \
    {                                                                           \
        _Pragma("unroll")                                                       \
        for (int it = 0; it < 4; it++) {                                        \
            float* d = &As[(size_t)(st) * BM * ALD + (arow + it*32) * ALD + ac]; \
            d[0] = wmma::__float_to_tf32(ra[it].x);                             \
            d[1] = wmma::__float_to_tf32(ra[it].y);                             \
            d[2] = wmma::__float_to_tf32(ra[it].z);                             \
            d[3] = wmma::__float_to_tf32(ra[it].w);                             \
            float* e = &Bs[(size_t)(st) * BK * BLD + (brow + it*8) * BLD + bc]; \
            e[0] = wmma::__float_to_tf32(rb[it].x);                             \
            e[1] = wmma::__float_to_tf32(rb[it].y);                             \
            e[2] = wmma::__float_to_tf32(rb[it].z);                             \
            e[3] = wmma::__float_to_tf32(rb[it].w);                             \
        }                                                                       \
    }

#define COMPUTE(st)                                                             \
    {                                                                           \
        const float* Ab = &As[(size_t)(st) * BM * ALD];                         \
        const float* Bb = &Bs[(size_t)(st) * BK * BLD];                         \
        _Pragma("unroll")                                                       \
        for (int ks = 0; ks < 4; ks++) {                                        \
            wmma::fragment<wmma::matrix_a, 16, 16, 8, wmma::precision::tf32, wmma::row_major> af[2]; \
            wmma::fragment<wmma::matrix_b, 16, 16, 8, wmma::precision::tf32, wmma::row_major> bf[4]; \
            _Pragma("unroll")                                                   \
            for (int i = 0; i < 2; i++)                                         \
                wmma::load_matrix_sync(af[i], Ab + (wm*32 + i*16) * ALD + ks*8, ALD); \
            _Pragma("unroll")                                                   \
            for (int j = 0; j < 4; j++)                                         \
                wmma::load_matrix_sync(bf[j], Bb + (ks*8) * BLD + wn*64 + j*16, BLD); \
            _Pragma("unroll")                                                   \
            for (int i = 0; i < 2; i++)                                         \
                _Pragma("unroll")                                               \
                for (int j = 0; j < 4; j++)                                     \
                    wmma::mma_sync(acc[i][j], af[i], bf[j], acc[i][j]);         \
        }                                                                       \
    }

    // prologue
    LOAD_TILES(0);
    STORE_TILES(0);
    __syncthreads();

    int cur = 0;
    for (int k0 = BK; k0 < DIMC; k0 += BK) {
        LOAD_TILES(k0);      // prefetch next tile into regs (overlaps compute)
        COMPUTE(cur);
        STORE_TILES(cur ^ 1);
        __syncthreads();
        cur ^= 1;
    }
    COMPUTE(cur);

#undef LOAD_TILES
#undef STORE_TILES
#undef COMPUTE

    if (MODE == 1) {
#pragma unroll
        for (int i = 0; i < 2; i++)
#pragma unroll
            for (int j = 0; j < 4; j++) {
                float* cptr = Cout + (size_t)(tileM + wm * 32 + i * 16) * N
                                   + tileN + wn * 64 + j * 16;
                wmma::store_matrix_sync(cptr, acc[i][j], N, wmma::mem_row_major);
            }
    } else {
        int nb    = blockIdx.x;
        int which = nb >> 4;     // 0:q 1:k 2:v
        int h     = nb & 15;
        int b     = tileM / SEQL;
        int t0    = tileM % SEQL;
        float* dstbase = (which == 0 ? g_q : (which == 1 ? g_k : g_v))
                       + (size_t)((b * NHEAD + h) * SEQL + t0) * HDIM;
#pragma unroll
        for (int i = 0; i < 2; i++)
#pragma unroll
            for (int j = 0; j < 4; j++) {
                float* cptr = dstbase + (size_t)(wm * 32 + i * 16) * HDIM + wn * 64 + j * 16;
                wmma::store_matrix_sync(cptr, acc[i][j], HDIM, wmma::mem_row_major);
            }
    }
}

// ---------------------------------------------------------------------------
// RoPE in-place on q and k: first 16 dims of each head, pairs (p, p+8)
// ---------------------------------------------------------------------------
__global__ void rope_kernel()
{
    int i = blockIdx.x * blockDim.x + threadIdx.x;
    const int per = BATCH * NHEAD * SEQL * 8;
    if (i >= 2 * per) return;
    int which = i / per;
    int r  = i % per;
    int bh = r / (SEQL * 8);
    int t  = (r / 8) % SEQL;
    int p  = r & 7;

    float inv = powf(10000.0f, -(float)p / 8.0f);
    float ang = (float)t * inv;
    float c = cosf(ang), s = sinf(ang);

    float* base = (which ? g_k : g_q) + (size_t)(bh * SEQL + t) * HDIM;
    float x1 = base[p];
    float x2 = base[p + 8];
    base[p]     = x1 * c - x2 * s;
    base[p + 8] = x2 * c + x1 * s;
}

// ---------------------------------------------------------------------------
// Tensor-core (wmma tf32) causal flash attention. BQ=BK=64, 256 thr (8 warps).
// Warp w: wm=w>>1 (16-row stripe), wn=w&1 (col half).
// S-phase: warp computes 16x32 of S.  PV-phase: warp computes 16x64 of O_j.
// O accumulated SIMT-side (thread t owns row t>>2, cols (t&3)*32..+32).
// K smem region is reused as the O_j staging buffer during PV.
// ---------------------------------------------------------------------------
#define AQ 64
#define AK 64
#define QLD 132
#define KLD 132
#define VLD 132
#define PLD 68
// float offsets in dynamic smem
#define OFF_QS 0
#define OFF_KS (OFF_QS + AQ*QLD)        // also O_j staging (64 x 128, ld 132)
#define OFF_VS (OFF_KS + AK*KLD)
#define OFF_PS (OFF_VS + AK*VLD)
#define OFF_AL (OFF_PS + AQ*PLD)        // Al[64], Lr[64]
#define ATTN_SMEM ((OFF_AL + 128) * 4)

__global__ void __launch_bounds__(256)
attn_kernel(float* __restrict__ Y)
{
    extern __shared__ float sm[];
    float* Qs = sm + OFF_QS;
    float* Ks = sm + OFF_KS;       // aliases Os in PV phase
    float* Vs = sm + OFF_VS;
    float* Ps = sm + OFF_PS;
    float* Al = sm + OFF_AL;
    float* Lr = Al + 64;

    const int tid = threadIdx.x;
    const int w   = tid >> 5;
    const int wm  = w >> 1;            // 0..3
    const int wn  = w & 1;             // 0..1
    const int bh  = blockIdx.y;        // 0..255
    const int qblk = blockIdx.x;       // 0..7
    const float scale = 0.08838834764831845f;   // 1/sqrt(128)

    const float* Qg = g_q + (size_t)bh * SEQL * HDIM;
    const float* Kg = g_k + (size_t)bh * SEQL * HDIM;
    const float* Vg = g_v + (size_t)bh * SEQL * HDIM;

    // Load Q block (scaled, tf32-rounded): 64x128
#pragma unroll
    for (int it = 0; it < 8; it++) {
        int idx = tid + it * 256;
        int row = idx >> 5;
        int c4  = (idx & 31) * 4;
        float4 v = *(const float4*)(Qg + (size_t)(qblk * AQ + row) * HDIM + c4);
        float* d = &Qs[row * QLD + c4];
        d[0] = wmma::__float_to_tf32(v.x * scale);
        d[1] = wmma::__float_to_tf32(v.y * scale);
        d[2] = wmma::__float_to_tf32(v.z * scale);
        d[3] = wmma::__float_to_tf32(v.w * scale);
    }

    // per-thread SIMT O accumulator: row rt, cols c0..c0+32
    const int rt = tid >> 2;
    const int c0 = (tid & 3) * 32;
    float o[32];
#pragma unroll
    for (int i = 0; i < 32; i++) o[i] = 0.0f;

    // softmax state lives in threads tid<64 (row = tid)
    float mr = -INFINITY, lr = 0.0f;

    for (int j = 0; j <= qblk; j++) {
        __syncthreads();   // prev SIMT update done with Ks(O) region; Vs free
        // Load K and V chunks (tf32-rounded)
#pragma unroll
        for (int it = 0; it < 8; it++) {
            int idx = tid + it * 256;
            int row = idx >> 5;
            int c4  = (idx & 31) * 4;
            float4 kv = *(const float4*)(Kg + (size_t)(j * AK + row) * HDIM + c4);
            float* dk = &Ks[row * KLD + c4];
            dk[0] = wmma::__float_to_tf32(kv.x);
            dk[1] = wmma::__float_to_tf32(kv.y);
            dk[2] = wmma::__float_to_tf32(kv.z);
            dk[3] = wmma::__float_to_tf32(kv.w);
            float4 vv = *(const float4*)(Vg + (size_t)(j * AK + row) * HDIM + c4);
            float* dv = &Vs[row * VLD + c4];
            dv[0] = wmma::__float_to_tf32(vv.x);
            dv[1] = wmma::__float_to_tf32(vv.y);
            dv[2] = wmma::__float_to_tf32(vv.z);
            dv[3] = wmma::__float_to_tf32(vv.w);
        }
        __syncthreads();

        // --- S = Q K^T : each warp 16x32 stripe ---
        {
            wmma::fragment<wmma::accumulator, 16, 16, 8, float> sacc[2];
#pragma unroll
            for (int jb = 0; jb < 2; jb++) wmma::fill_fragment(sacc[jb], 0.0f);
#pragma unroll
            for (int kk = 0; kk < HDIM; kk += 8) {
                wmma::fragment<wmma::matrix_a, 16, 16, 8, wmma::precision::tf32, wmma::row_major> af;
                wmma::load_matrix_sync(af, Qs + (wm * 16) * QLD + kk, QLD);
#pragma unroll
                for (int jb = 0; jb < 2; jb++) {
                    wmma::fragment<wmma::matrix_b, 16, 16, 8, wmma::precision::tf32, wmma::col_major> bf;
                    wmma::load_matrix_sync(bf, Ks + (wn * 32 + jb * 16) * KLD + kk, KLD);
                    wmma::mma_sync(sacc[jb], af, bf, sacc[jb]);
                }
            }
#pragma unroll
            for (int jb = 0; jb < 2; jb++)
                wmma::store_matrix_sync(Ps + (wm * 16) * PLD + wn * 32 + jb * 16,
                                        sacc[jb], PLD, wmma::mem_row_major);
        }
        __syncthreads();

        // --- online softmax on rows (threads 0..63) ---
        if (tid < 64) {
            const int cmax = (j == qblk) ? tid : 63;
            float* prow = &Ps[tid * PLD];
            float mx = -INFINITY;
            for (int c = 0; c <= cmax; c++) mx = fmaxf(mx, prow[c]);
            float mnew  = fmaxf(mr, mx);
            float alpha = __expf(mr - mnew);
            float rs = 0.0f;
            for (int c = 0; c < 64; c++) {
                float p = (c <= cmax) ? __expf(prow[c] - mnew) : 0.0f;
                prow[c] = wmma::__float_to_tf32(p);
                rs += p;
            }
            lr = lr * alpha + rs;
            mr = mnew;
            Al[tid] = alpha;
        }
        __syncthreads();

        // --- O_j = P V : each warp 16x64 stripe, staged into Ks region ---
        {
            wmma::fragment<wmma::accumulator, 16, 16, 8, float> oacc[4];
#pragma unroll
            for (int jn = 0; jn < 4; jn++) wmma::fill_fragment(oacc[jn], 0.0f);
#pragma unroll
            for (int kc = 0; kc < AK; kc += 8) {
                wmma::fragment<wmma::matrix_a, 16, 16, 8, wmma::precision::tf32, wmma::row_major> af;
                wmma::load_matrix_sync(af, Ps + (wm * 16) * PLD + kc, PLD);
#pragma unroll
                for (int jn = 0; jn < 4; jn++) {
                    wmma::fragment<wmma::matrix_b, 16, 16, 8, wmma::precision::tf32, wmma::row_major> bf;
                    wmma::load_matrix_sync(bf, Vs + kc * VLD + wn * 64 + jn * 16, VLD);
                    wmma::mma_sync(oacc[jn], af, bf, oacc[jn]);
                }
            }
#pragma unroll
            for (int jn = 0; jn < 4; jn++)
                wmma::store_matrix_sync(Ks + (wm * 16) * KLD + wn * 64 + jn * 16,
                                        oacc[jn], KLD, wmma::mem_row_major);
        }
        __syncthreads();

        // --- SIMT accumulate: o = alpha*o + O_j ---
        {
            float a = Al[rt];
            const float* orow = &Ks[rt * KLD + c0];
#pragma unroll
            for (int i4 = 0; i4 < 32; i4 += 4) {
                float4 v = *(const float4*)(orow + i4);
                o[i4+0] = o[i4+0] * a + v.x;
                o[i4+1] = o[i4+1] * a + v.y;
                o[i4+2] = o[i4+2] * a + v.z;
                o[i4+3] = o[i4+3] * a + v.w;
            }
        }
    }

    // publish row sums, normalize, write out
    if (tid < 64) Lr[tid] = lr;
    __syncthreads();
    {
        float inv = 1.0f / Lr[rt];
        int b = bh >> 4, h = bh & 15;
        int t = qblk * AQ + rt;
        float* dst = Y + (size_t)(b * SEQL + t) * DIMC + h * HDIM + c0;
#pragma unroll
        for (int i4 = 0; i4 < 32; i4 += 4) {
            float4 v = { o[i4+0]*inv, o[i4+1]*inv, o[i4+2]*inv, o[i4+3]*inv };
            *(float4*)(dst + i4) = v;
        }
    }
}

// ---------------------------------------------------------------------------
extern "C" void kernel_launch(void* const* d_in, const int* in_sizes, int n_in,
                              void* d_out, int out_size)
{
    const float* x    = (const float*)d_in[0];   // [16,512,2048]
    const float* Wqkv = (const float*)d_in[1];   // [2048,6144]
    const float* Wout = (const float*)d_in[2];   // [2048,2048]
    float* out = (float*)d_out;                  // [16,512,2048]

    static bool attrs_set = false;
    if (!attrs_set) {
        cudaFuncSetAttribute(gemm_tf32_kernel<0>, cudaFuncAttributeMaxDynamicSharedMemorySize, GEMM_SMEM);
        cudaFuncSetAttribute(gemm_tf32_kernel<1>, cudaFuncAttributeMaxDynamicSharedMemorySize, GEMM_SMEM);
        cudaFuncSetAttribute(attn_kernel, cudaFuncAttributeMaxDynamicSharedMemorySize, ATTN_SMEM);
        attrs_set = true;
    }

    // 1) QKV GEMM with fused scatter to [B,H,T,hd]
    gemm_tf32_kernel<0><<<dim3(NQKV / BN, MTOT / BM), 256, GEMM_SMEM>>>(x, Wqkv, nullptr, NQKV);

    // 2) RoPE on q,k (first 16 dims)
    {
        int total = 2 * BATCH * NHEAD * SEQL * 8;
        rope_kernel<<<(total + 255) / 256, 256>>>();
    }

    // 3) Causal flash attention (wmma tf32)
    {
        float* yp = nullptr;
        cudaGetSymbolAddress((void**)&yp, g_y);
        attn_kernel<<<dim3(SEQL / AQ, BATCH * NHEAD), 256, ATTN_SMEM>>>(yp);
    }

    // 4) Output projection
    gemm_tf32_kernel<1><<<dim3(DIMC / BN, MTOT / BM), 256, GEMM_SMEM>>>(nullptr, Wout, out, DIMC);
}

// round 5
// speedup vs baseline: 1.5829x; 1.5829x over previous
#include <cuda_runtime.h>
#include <mma.h>
#include <cmath>

using namespace nvcuda;

#define BATCH 16
#define SEQL  512
#define DIMC  2048
#define NHEAD 16
#define HDIM  128
#define NQKV  6144
#define MTOT  (BATCH*SEQL)   // 8192

// Scratch (device globals: allocation-guard safe)
__device__ float g_q[(size_t)BATCH*NHEAD*SEQL*HDIM];  // [B,H,T,hd]
__device__ float g_k[(size_t)BATCH*NHEAD*SEQL*HDIM];
__device__ float g_v[(size_t)BATCH*NHEAD*SEQL*HDIM];
__device__ float g_y[(size_t)MTOT*DIMC];              // attention out, [B*T, C]

// ---------------------------------------------------------------------------
// TF32 GEMM, double-buffered, 128x256 CTA tile, 64x64 warp tiles (8 warps)
// C[M,N] = A[M,2048] * B[2048,N]
// MODE 0: A = x, N=6144, epilogue scatters q/k/v into [B,H,T,hd] layout
// MODE 1: A = g_y, N=2048, epilogue writes Cout row-major
// ---------------------------------------------------------------------------
#define BM 128
#define BN 256
#define BK 32
#define ALD (BK + 4)    // 36
#define BLD (BN + 4)    // 260
#define GEMM_SMEM ((2*BM*ALD + 2*BK*BLD) * 4)   // 103424 B

template<int MODE>
__global__ void __launch_bounds__(256, 1)
gemm_tf32_kernel(const float* __restrict__ A, const float* __restrict__ Bmat,
                 float* __restrict__ Cout, int N)
{
    extern __shared__ float sm[];
    float* As = sm;                       // [2][BM][ALD]
    float* Bs = sm + 2 * BM * ALD;        // [2][BK][BLD]

    const int tid  = threadIdx.x;
    const int warp = tid >> 5;
    const int wm   = warp >> 2;      // 0..1  (rows of 64)
    const int wn   = warp & 3;       // 0..3  (cols of 64)
    const int tileM = blockIdx.y * BM;
    const int tileN = blockIdx.x * BN;

    const float* Aptr = (MODE == 1) ? g_y : A;

    const int arow = tid >> 3;       // 0..31 base row (stride 32 over 4 its)
    const int ac   = (tid & 7) * 4;
    const int brow = tid >> 6;       // 0..3 base row (stride 4 over 8 its)
    const int bc   = (tid & 63) * 4;

    wmma::fragment<wmma::accumulator, 16, 16, 8, float> acc[4][4];
#pragma unroll
    for (int i = 0; i < 4; i++)
#pragma unroll
        for (int j = 0; j < 4; j++) wmma::fill_fragment(acc[i][j], 0.0f);

    float4 ra[4], rb[8];

#define LOAD_TILES(k0)                                                          \
    {                                                                           \
        _Pragma("unroll")                                                       \
        for (int it = 0; it < 4; it++)                                          \
            ra[it] = *(const float4*)(Aptr + (size_t)(tileM + arow + it*32) * DIMC + (k0) + ac); \
        _Pragma("unroll")                                                       \
        for (int it = 0; it < 8; it++)                                          \
            rb[it] = *(const float4*)(Bmat + (size_t)((k0) + brow + it*4) * N + tileN + bc); \
    }

#define STORE_TILES(st)                                                         \
    {                                                                           \
        _Pragma("unroll")                                                       \
        for (int it = 0; it < 4; it++) {                                        \
            float* d = &As[(size_t)(st) * BM * ALD + (arow + it*32) * ALD + ac]; \
            d[0] = wmma::__float_to_tf32(ra[it].x);                             \
            d[1] = wmma::__float_to_tf32(ra[it].y);                             \
            d[2] = wmma::__float_to_tf32(ra[it].z);                             \
            d[3] = wmma::__float_to_tf32(ra[it].w);                             \
        }                                                                       \
        _Pragma("unroll")                                                       \
        for (int it = 0; it < 8; it++) {                                        \
            float* e = &Bs[(size_t)(st) * BK * BLD + (brow + it*4) * BLD + bc]; \
            e[0] = wmma::__float_to_tf32(rb[it].x);                             \
            e[1] = wmma::__float_to_tf32(rb[it].y);                             \
            e[2] = wmma::__float_to_tf32(rb[it].z);                             \
            e[3] = wmma::__float_to_tf32(rb[it].w);                             \
        }                                                                       \
    }

#define COMPUTE(st)                                                             \
    {                                                                           \
        const float* Ab = &As[(size_t)(st) * BM * ALD];                         \
        const float* Bb = &Bs[(size_t)(st) * BK * BLD];                         \
        _Pragma("unroll")                                                       \
        for (int ks = 0; ks < 4; ks++) {                                        \
            wmma::fragment<wmma::matrix_a, 16, 16, 8, wmma::precision::tf32, wmma::row_major> af[4]; \
            wmma::fragment<wmma::matrix_b, 16, 16, 8, wmma::precision::tf32, wmma::row_major> bf[4]; \
            _Pragma("unroll")                                                   \
            for (int i = 0; i < 4; i++)                                         \
                wmma::load_matrix_sync(af[i], Ab + (wm*64 + i*16) * ALD + ks*8, ALD); \
            _Pragma("unroll")                                                   \
            for (int j = 0; j < 4; j++)                                         \
                wmma::load_matrix_sync(bf[j], Bb + (ks*8) * BLD + wn*64 + j*16, BLD); \
            _Pragma("unroll")                                                   \
            for (int i = 0; i < 4; i++)                                         \
                _Pragma("unroll")                                               \
                for (int j = 0; j < 4; j++)                                     \
                    wmma::mma_sync(acc[i][j], af[i], bf[j], acc[i][j]);         \
        }                                                                       \
    }

    // prologue
    LOAD_TILES(0);
    STORE_TILES(0);
    __syncthreads();

    int cur = 0;
    for (int k0 = BK; k0 < DIMC; k0 += BK) {
        LOAD_TILES(k0);      // prefetch next tile into regs (overlaps compute)
        COMPUTE(cur);
        STORE_TILES(cur ^ 1);
        __syncthreads();
        cur ^= 1;
    }
    COMPUTE(cur);

#undef LOAD_TILES
#undef STORE_TILES
#undef COMPUTE

    if (MODE == 1) {
#pragma unroll
        for (int i = 0; i < 4; i++)
#pragma unroll
            for (int j = 0; j < 4; j++) {
                float* cptr = Cout + (size_t)(tileM + wm * 64 + i * 16) * N
                                   + tileN + wn * 64 + j * 16;
                wmma::store_matrix_sync(cptr, acc[i][j], N, wmma::mem_row_major);
            }
    } else {
        // each warp's 64-col stripe lies in one 128-col head block
        int colw  = tileN + wn * 64;
        int nb128 = colw >> 7;          // global 128-col block index
        int which = nb128 >> 4;         // 0:q 1:k 2:v
        int h     = nb128 & 15;
        int cin   = colw & 127;         // 0 or 64
        int b     = tileM / SEQL;
        int t0    = tileM % SEQL;
        float* dstbase = (which == 0 ? g_q : (which == 1 ? g_k : g_v))
                       + (size_t)((b * NHEAD + h) * SEQL + t0 + wm * 64) * HDIM + cin;
#pragma unroll
        for (int i = 0; i < 4; i++)
#pragma unroll
            for (int j = 0; j < 4; j++) {
                float* cptr = dstbase + (size_t)(i * 16) * HDIM + j * 16;
                wmma::store_matrix_sync(cptr, acc[i][j], HDIM, wmma::mem_row_major);
            }
    }
}

// ---------------------------------------------------------------------------
// RoPE in-place on q and k: first 16 dims of each head, pairs (p, p+8)
// ---------------------------------------------------------------------------
__global__ void rope_kernel()
{
    int i = blockIdx.x * blockDim.x + threadIdx.x;
    const int per = BATCH * NHEAD * SEQL * 8;
    if (i >= 2 * per) return;
    int which = i / per;
    int r  = i % per;
    int bh = r / (SEQL * 8);
    int t  = (r / 8) % SEQL;
    int p  = r & 7;

    float inv = powf(10000.0f, -(float)p / 8.0f);
    float ang = (float)t * inv;
    float c = cosf(ang), s = sinf(ang);

    float* base = (which ? g_k : g_q) + (size_t)(bh * SEQL + t) * HDIM;
    float x1 = base[p];
    float x2 = base[p + 8];
    base[p]     = x1 * c - x2 * s;
    base[p + 8] = x2 * c + x1 * s;
}

// ---------------------------------------------------------------------------
// Causal flash attention, fp32 SIMT. BQ=BK=64, 256 threads. (round-2 version)
// ---------------------------------------------------------------------------
#define AQ 64
#define AK 64
#define KTLD 65   // padded ld of transposed K

__global__ void __launch_bounds__(256)
attn_kernel(float* __restrict__ Y)
{
    extern __shared__ float smattn[];
    float* Qs = smattn;                    // 64*128
    float* Kt = Qs + AQ * HDIM;            // 128*65 (transposed K)
    float* Vs = Kt + HDIM * KTLD;          // 64*128
    float* Ps = Vs + AK * HDIM;            // 64*64

    const int tid = threadIdx.x;
    const int w   = tid >> 5;
    const int l   = tid & 31;
    const int bh  = blockIdx.y;            // 0..255
    const int qblk = blockIdx.x;           // 0..7
    const float scale = 0.08838834764831845f;   // 1/sqrt(128)

    const float* Qg = g_q + (size_t)bh * SEQL * HDIM;
    const float* Kg = g_k + (size_t)bh * SEQL * HDIM;
    const float* Vg = g_v + (size_t)bh * SEQL * HDIM;

#pragma unroll
    for (int it = 0; it < 8; it++) {
        int idx = tid + it * 256;
        int row = idx >> 5;
        int c4  = idx & 31;
        float4 v = *(const float4*)(Qg + (size_t)(qblk * AQ + row) * HDIM + c4 * 4);
        v.x *= scale; v.y *= scale; v.z *= scale; v.w *= scale;
        *(float4*)&Qs[row * HDIM + c4 * 4] = v;
    }

    float o[8][4];
    float mr[8], lr[8];
#pragma unroll
    for (int r = 0; r < 8; r++) {
        mr[r] = -INFINITY; lr[r] = 0.0f;
        o[r][0] = o[r][1] = o[r][2] = o[r][3] = 0.0f;
    }

    for (int j = 0; j <= qblk; j++) {
        __syncthreads();
#pragma unroll
        for (int it = 0; it < 8; it++) {
            int idx = tid + it * 256;
            int col = idx >> 5;
            int c4  = idx & 31;
            int kk  = c4 * 4;
            float4 kv = *(const float4*)(Kg + (size_t)(j * AK + col) * HDIM + kk);
            Kt[(kk + 0) * KTLD + col] = kv.x;
            Kt[(kk + 1) * KTLD + col] = kv.y;
            Kt[(kk + 2) * KTLD + col] = kv.z;
            Kt[(kk + 3) * KTLD + col] = kv.w;
            float4 vv = *(const float4*)(Vg + (size_t)(j * AK + col) * HDIM + kk);
            *(float4*)&Vs[col * HDIM + kk] = vv;
        }
        __syncthreads();

        float s0[8], s1[8];
#pragma unroll
        for (int r = 0; r < 8; r++) { s0[r] = 0.0f; s1[r] = 0.0f; }
        for (int kk = 0; kk < HDIM; kk += 4) {
            float ka[4], kb[4];
#pragma unroll
            for (int u = 0; u < 4; u++) {
                ka[u] = Kt[(kk + u) * KTLD + l];
                kb[u] = Kt[(kk + u) * KTLD + l + 32];
            }
#pragma unroll
            for (int r = 0; r < 8; r++) {
                float4 qv = *(const float4*)&Qs[(w * 8 + r) * HDIM + kk];
                s0[r] += qv.x * ka[0] + qv.y * ka[1] + qv.z * ka[2] + qv.w * ka[3];
                s1[r] += qv.x * kb[0] + qv.y * kb[1] + qv.z * kb[2] + qv.w * kb[3];
            }
        }

        if (j == qblk) {
#pragma unroll
            for (int r = 0; r < 8; r++) {
                int row = w * 8 + r;
                if (l > row)      s0[r] = -1e30f;
                if (l + 32 > row) s1[r] = -1e30f;
            }
        }

#pragma unroll
        for (int r = 0; r < 8; r++) {
            float mx = fmaxf(s0[r], s1[r]);
#pragma unroll
            for (int off = 16; off; off >>= 1)
                mx = fmaxf(mx, __shfl_xor_sync(0xffffffffu, mx, off));
            float mnew  = fmaxf(mr[r], mx);
            float alpha = __expf(mr[r] - mnew);
            float p0 = __expf(s0[r] - mnew);
            float p1 = __expf(s1[r] - mnew);
            float rs = p0 + p1;
#pragma unroll
            for (int off = 16; off; off >>= 1)
                rs += __shfl_xor_sync(0xffffffffu, rs, off);
            lr[r] = lr[r] * alpha + rs;
            mr[r] = mnew;
            o[r][0] *= alpha; o[r][1] *= alpha; o[r][2] *= alpha; o[r][3] *= alpha;
            Ps[(w * 8 + r) * AK + l]      = p0;
            Ps[(w * 8 + r) * AK + l + 32] = p1;
        }
        __syncwarp();

        for (int col = 0; col < AK; col++) {
            float4 vv = *(const float4*)&Vs[col * HDIM + 4 * l];
#pragma unroll
            for (int r = 0; r < 8; r++) {
                float p = Ps[(w * 8 + r) * AK + col];
                o[r][0] += p * vv.x;
                o[r][1] += p * vv.y;
                o[r][2] += p * vv.z;
                o[r][3] += p * vv.w;
            }
        }
    }

    int b = bh >> 4, h = bh & 15;
#pragma unroll
    for (int r = 0; r < 8; r++) {
        float inv = 1.0f / lr[r];
        int t = qblk * AQ + w * 8 + r;
        float4 ov;
        ov.x = o[r][0] * inv; ov.y = o[r][1] * inv;
        ov.z = o[r][2] * inv; ov.w = o[r][3] * inv;
        *(float4*)(Y + (size_t)(b * SEQL + t) * DIMC + h * HDIM + 4 * l) = ov;
    }
}

// ---------------------------------------------------------------------------
extern "C" void kernel_launch(void* const* d_in, const int* in_sizes, int n_in,
                              void* d_out, int out_size)
{
    const float* x    = (const float*)d_in[0];   // [16,512,2048]
    const float* Wqkv = (const float*)d_in[1];   // [2048,6144]
    const float* Wout = (const float*)d_in[2];   // [2048,2048]
    float* out = (float*)d_out;                  // [16,512,2048]

    static bool attrs_set = false;
    if (!attrs_set) {
        cudaFuncSetAttribute(gemm_tf32_kernel<0>, cudaFuncAttributeMaxDynamicSharedMemorySize, GEMM_SMEM);
        cudaFuncSetAttribute(gemm_tf32_kernel<1>, cudaFuncAttributeMaxDynamicSharedMemorySize, GEMM_SMEM);
        size_t smem = (size_t)(AQ * HDIM + HDIM * KTLD + AK * HDIM + AQ * AK) * sizeof(float);
        cudaFuncSetAttribute(attn_kernel, cudaFuncAttributeMaxDynamicSharedMemorySize, (int)smem);
        attrs_set = true;
    }

    // 1) QKV GEMM with fused scatter to [B,H,T,hd]
    gemm_tf32_kernel<0><<<dim3(NQKV / BN, MTOT / BM), 256, GEMM_SMEM>>>(x, Wqkv, nullptr, NQKV);

    // 2) RoPE on q,k (first 16 dims)
    {
        int total = 2 * BATCH * NHEAD * SEQL * 8;
        rope_kernel<<<(total + 255) / 256, 256>>>();
    }

    // 3) Causal flash attention (SIMT fp32)
    {
        size_t smem = (size_t)(AQ * HDIM + HDIM * KTLD + AK * HDIM + AQ * AK) * sizeof(float);
        float* yp = nullptr;
        cudaGetSymbolAddress((void**)&yp, g_y);
        attn_kernel<<<dim3(SEQL / AQ, BATCH * NHEAD), 256, smem>>>(yp);
    }

    // 4) Output projection
    gemm_tf32_kernel<1><<<dim3(DIMC / BN, MTOT / BM), 256, GEMM_SMEM>>>(nullptr, Wout, out, DIMC);
}